// round 8
// baseline (speedup 1.0000x reference)
#include <cuda_runtime.h>

#define ROWS  8192
#define COLS  16384
#define BLOCK 512
#define NWARPS (BLOCK / 32)

// Allocation-free scratch: accumulator + completion counter.
__device__ float    g_acc   = 0.0f;
__device__ unsigned g_count = 0;

// 256-bit non-coherent global load (sm_100+ / PTX 8.8): one LDG.E.256.
__device__ __forceinline__ void ldg256(const float* __restrict__ a,
                                       float& f0, float& f1, float& f2, float& f3,
                                       float& f4, float& f5, float& f6, float& f7)
{
    asm volatile(
        "ld.global.nc.v8.f32 {%0, %1, %2, %3, %4, %5, %6, %7}, [%8];"
        : "=f"(f0), "=f"(f1), "=f"(f2), "=f"(f3),
          "=f"(f4), "=f"(f5), "=f"(f6), "=f"(f7)
        : "l"(a));
}

__device__ __forceinline__ void epilogue(float s, float* __restrict__ out,
                                         int nblocks)
{
    // Warp reduce
    #pragma unroll
    for (int o = 16; o > 0; o >>= 1)
        s += __shfl_down_sync(0xffffffffu, s, o);

    __shared__ float ws[NWARPS];
    if ((threadIdx.x & 31) == 0) ws[threadIdx.x >> 5] = s;
    __syncthreads();

    if (threadIdx.x == 0) {
        float t = ws[0];
        #pragma unroll
        for (int w = 1; w < NWARPS; w++) t += ws[w];

        float h = fmaxf(t - 1.0f, 0.0f);
        atomicAdd(&g_acc, h);
        __threadfence();
        unsigned done = atomicAdd(&g_count, 1u);
        if (done == (unsigned)nblocks - 1u) {
            float total = *(volatile float*)&g_acc;
            out[0] = total / (float)nblocks;
            // Reset for next graph replay.
            *(volatile float*)&g_acc = 0.0f;
            *(volatile unsigned*)&g_count = 0u;
            __threadfence();
        }
    }
}

// One CTA per row, 512 threads. Each thread issues 4 fully-unrolled 256-bit
// loads (LDG.E.256) covering its 32 floats: half the LSU issue slots and
// L1tex wavefront-queue entries per byte vs 8x LDG.128.
__global__ void __launch_bounds__(BLOCK) bloss_v8_kernel(
    const float* __restrict__ B, float* __restrict__ out)
{
    // Lane-contiguous 32B chunks: thread t covers [t*8, t*8+8) within each
    // of 4 batches of 4096 floats.
    const float* __restrict__ p =
        B + (size_t)blockIdx.x * COLS + (size_t)threadIdx.x * 8;

    float a0,a1,a2,a3,a4,a5,a6,a7;
    float b0,b1,b2,b3,b4,b5,b6,b7;
    float c0,c1,c2,c3,c4,c5,c6,c7;
    float d0,d1,d2,d3,d4,d5,d6,d7;

    ldg256(p,                 a0,a1,a2,a3,a4,a5,a6,a7);
    ldg256(p + 1 * BLOCK * 8, b0,b1,b2,b3,b4,b5,b6,b7);
    ldg256(p + 2 * BLOCK * 8, c0,c1,c2,c3,c4,c5,c6,c7);
    ldg256(p + 3 * BLOCK * 8, d0,d1,d2,d3,d4,d5,d6,d7);

    float sa = ((a0 + a1) + (a2 + a3)) + ((a4 + a5) + (a6 + a7));
    float sb = ((b0 + b1) + (b2 + b3)) + ((b4 + b5) + (b6 + b7));
    float sc = ((c0 + c1) + (c2 + c3)) + ((c4 + c5) + (c6 + c7));
    float sd = ((d0 + d1) + (d2 + d3)) + ((d4 + d5) + (d6 + d7));

    epilogue((sa + sb) + (sc + sd), out, ROWS);
}

// Generic fallback (any cols divisible by 4): one row per CTA, LDG.128 loop.
__global__ void __launch_bounds__(BLOCK) bloss_generic_kernel(
    const float* __restrict__ B, float* __restrict__ out, int cols)
{
    const float4* __restrict__ p =
        reinterpret_cast<const float4*>(B + (size_t)blockIdx.x * (size_t)cols);
    const int n4 = cols >> 2;

    float s0 = 0.0f, s1 = 0.0f, s2 = 0.0f, s3 = 0.0f;
    int i = threadIdx.x;
    for (; i + 3 * BLOCK < n4; i += 4 * BLOCK) {
        float4 v0 = p[i];
        float4 v1 = p[i + BLOCK];
        float4 v2 = p[i + 2 * BLOCK];
        float4 v3 = p[i + 3 * BLOCK];
        s0 += (v0.x + v0.y) + (v0.z + v0.w);
        s1 += (v1.x + v1.y) + (v1.z + v1.w);
        s2 += (v2.x + v2.y) + (v2.z + v2.w);
        s3 += (v3.x + v3.y) + (v3.z + v3.w);
    }
    for (; i < n4; i += BLOCK) {
        float4 v = p[i];
        s0 += (v.x + v.y) + (v.z + v.w);
    }
    epilogue((s0 + s1) + (s2 + s3), out, ROWS);
}

extern "C" void kernel_launch(void* const* d_in, const int* in_sizes, int n_in,
                              void* d_out, int out_size)
{
    const float* B = (const float*)d_in[0];
    const int rows = ROWS;                   // 8192 per problem spec
    const int cols = in_sizes[0] / rows;     // 16384

    if (cols == COLS)
        bloss_v8_kernel<<<rows, BLOCK>>>(B, (float*)d_out);
    else
        bloss_generic_kernel<<<rows, BLOCK>>>(B, (float*)d_out, cols);
}

// round 9
// speedup vs baseline: 1.0333x; 1.0333x over previous
#include <cuda_runtime.h>

#define ROWS  8192
#define COLS  16384
#define BLOCK 256
#define NWARPS (BLOCK / 32)

// Allocation-free scratch: accumulator + completion counter.
__device__ float    g_acc   = 0.0f;
__device__ unsigned g_count = 0;

__device__ __forceinline__ void epilogue(float s, float* __restrict__ out,
                                         int nblocks)
{
    // Warp reduce
    #pragma unroll
    for (int o = 16; o > 0; o >>= 1)
        s += __shfl_down_sync(0xffffffffu, s, o);

    __shared__ float ws[NWARPS];
    if ((threadIdx.x & 31) == 0) ws[threadIdx.x >> 5] = s;
    __syncthreads();

    if (threadIdx.x == 0) {
        float t = ws[0];
        #pragma unroll
        for (int w = 1; w < NWARPS; w++) t += ws[w];

        float h = fmaxf(t - 1.0f, 0.0f);
        atomicAdd(&g_acc, h);
        __threadfence();
        unsigned done = atomicAdd(&g_count, 1u);
        if (done == (unsigned)nblocks - 1u) {
            float total = *(volatile float*)&g_acc;
            out[0] = total / (float)nblocks;
            // Reset for next graph replay.
            *(volatile float*)&g_acc = 0.0f;
            *(volatile unsigned*)&g_count = 0u;
            __threadfence();
        }
    }
}

// Sum one batch of 8 front-batched LDG.128 at immediate offsets.
__device__ __forceinline__ float sum_batch8(const float4* __restrict__ p)
{
    float4 v0 = p[0];
    float4 v1 = p[1 * BLOCK];
    float4 v2 = p[2 * BLOCK];
    float4 v3 = p[3 * BLOCK];
    float4 v4 = p[4 * BLOCK];
    float4 v5 = p[5 * BLOCK];
    float4 v6 = p[6 * BLOCK];
    float4 v7 = p[7 * BLOCK];

    float s0 = (v0.x + v0.y) + (v0.z + v0.w);
    float s1 = (v1.x + v1.y) + (v1.z + v1.w);
    float s2 = (v2.x + v2.y) + (v2.z + v2.w);
    float s3 = (v3.x + v3.y) + (v3.z + v3.w);
    float s4 = (v4.x + v4.y) + (v4.z + v4.w);
    float s5 = (v5.x + v5.y) + (v5.z + v5.w);
    float s6 = (v6.x + v6.y) + (v6.z + v6.w);
    float s7 = (v7.x + v7.y) + (v7.z + v7.w);

    return ((s0 + s1) + (s2 + s3)) + ((s4 + s5) + (s6 + s7));
}

// One CTA per row, 256 threads. Each thread owns 16 float4, processed as two
// fully-unrolled batches of 8 LDG.128 (8-deep MLP, moderate register
// pressure -> ~6 resident CTAs per SM for more independent row streams).
__global__ void __launch_bounds__(BLOCK) bloss_unrolled_kernel(
    const float* __restrict__ B, float* __restrict__ out)
{
    const float4* __restrict__ p =
        reinterpret_cast<const float4*>(B + (size_t)blockIdx.x * COLS)
        + threadIdx.x;

    float sA = sum_batch8(p);
    float sB = sum_batch8(p + 8 * BLOCK);

    epilogue(sA + sB, out, ROWS);
}

// Generic fallback (any cols divisible by 4): one row per CTA, LDG.128 loop.
__global__ void __launch_bounds__(BLOCK) bloss_generic_kernel(
    const float* __restrict__ B, float* __restrict__ out, int cols)
{
    const float4* __restrict__ p =
        reinterpret_cast<const float4*>(B + (size_t)blockIdx.x * (size_t)cols);
    const int n4 = cols >> 2;

    float s0 = 0.0f, s1 = 0.0f, s2 = 0.0f, s3 = 0.0f;
    int i = threadIdx.x;
    for (; i + 3 * BLOCK < n4; i += 4 * BLOCK) {
        float4 v0 = p[i];
        float4 v1 = p[i + BLOCK];
        float4 v2 = p[i + 2 * BLOCK];
        float4 v3 = p[i + 3 * BLOCK];
        s0 += (v0.x + v0.y) + (v0.z + v0.w);
        s1 += (v1.x + v1.y) + (v1.z + v1.w);
        s2 += (v2.x + v2.y) + (v2.z + v2.w);
        s3 += (v3.x + v3.y) + (v3.z + v3.w);
    }
    for (; i < n4; i += BLOCK) {
        float4 v = p[i];
        s0 += (v.x + v.y) + (v.z + v.w);
    }
    epilogue((s0 + s1) + (s2 + s3), out, ROWS);
}

extern "C" void kernel_launch(void* const* d_in, const int* in_sizes, int n_in,
                              void* d_out, int out_size)
{
    const float* B = (const float*)d_in[0];
    const int rows = ROWS;                   // 8192 per problem spec
    const int cols = in_sizes[0] / rows;     // 16384

    if (cols == COLS)
        bloss_unrolled_kernel<<<rows, BLOCK>>>(B, (float*)d_out);
    else
        bloss_generic_kernel<<<rows, BLOCK>>>(B, (float*)d_out, cols);
}

// round 10
// speedup vs baseline: 1.0531x; 1.0192x over previous
#include <cuda_runtime.h>

#define ROWS  8192
#define COLS  16384
#define BLOCK 512
#define NWARPS (BLOCK / 32)

// Allocation-free scratch: accumulator + completion counter.
__device__ float    g_acc   = 0.0f;
__device__ unsigned g_count = 0;

__device__ __forceinline__ void epilogue(float s, float* __restrict__ out,
                                         int nblocks)
{
    // Warp reduce
    #pragma unroll
    for (int o = 16; o > 0; o >>= 1)
        s += __shfl_down_sync(0xffffffffu, s, o);

    __shared__ float ws[NWARPS];
    if ((threadIdx.x & 31) == 0) ws[threadIdx.x >> 5] = s;
    __syncthreads();

    if (threadIdx.x < 32) {
        // Warp-parallel tail: 16 partials reduced by shuffle tree.
        float t = (threadIdx.x < NWARPS) ? ws[threadIdx.x] : 0.0f;
        #pragma unroll
        for (int o = NWARPS / 2; o > 0; o >>= 1)
            t += __shfl_down_sync(0xffffffffu, t, o);

        if (threadIdx.x == 0) {
            float h = fmaxf(t - 1.0f, 0.0f);
            atomicAdd(&g_acc, h);
            // Release-ordered count increment: orders the g_acc add before
            // the counter bump without a full MEMBAR.GPU.
            unsigned done;
            asm volatile("atom.add.release.gpu.u32 %0, [%1], 1;"
                         : "=r"(done) : "l"(&g_count) : "memory");
            if (done == (unsigned)nblocks - 1u) {
                // Acquire-ordered read: all release-ordered g_acc adds visible.
                float total;
                asm volatile("ld.acquire.gpu.f32 %0, [%1];"
                             : "=f"(total) : "l"(&g_acc) : "memory");
                out[0] = total / (float)nblocks;
                // Reset for next graph replay.
                *(volatile float*)&g_acc = 0.0f;
                asm volatile("st.release.gpu.u32 [%0], 0;"
                             :: "l"(&g_count) : "memory");
            }
        }
    }
}

// One CTA per row, 512 threads, each thread loads exactly 8 float4 fully
// unrolled (8 front-batched LDG.128 at immediate offsets). This load stream
// measures at the chip LTS throughput cap (~6.9 TB/s) — do not touch.
__global__ void __launch_bounds__(BLOCK) bloss_unrolled_kernel(
    const float* __restrict__ B, float* __restrict__ out)
{
    const float4* __restrict__ p =
        reinterpret_cast<const float4*>(B + (size_t)blockIdx.x * COLS)
        + threadIdx.x;

    float4 v0 = p[0];
    float4 v1 = p[1 * BLOCK];
    float4 v2 = p[2 * BLOCK];
    float4 v3 = p[3 * BLOCK];
    float4 v4 = p[4 * BLOCK];
    float4 v5 = p[5 * BLOCK];
    float4 v6 = p[6 * BLOCK];
    float4 v7 = p[7 * BLOCK];

    float s0 = (v0.x + v0.y) + (v0.z + v0.w);
    float s1 = (v1.x + v1.y) + (v1.z + v1.w);
    float s2 = (v2.x + v2.y) + (v2.z + v2.w);
    float s3 = (v3.x + v3.y) + (v3.z + v3.w);
    float s4 = (v4.x + v4.y) + (v4.z + v4.w);
    float s5 = (v5.x + v5.y) + (v5.z + v5.w);
    float s6 = (v6.x + v6.y) + (v6.z + v6.w);
    float s7 = (v7.x + v7.y) + (v7.z + v7.w);

    float s = ((s0 + s1) + (s2 + s3)) + ((s4 + s5) + (s6 + s7));
    epilogue(s, out, ROWS);
}

// Generic fallback (any cols divisible by 4): one row per CTA, LDG.128 loop.
__global__ void __launch_bounds__(BLOCK) bloss_generic_kernel(
    const float* __restrict__ B, float* __restrict__ out, int cols)
{
    const float4* __restrict__ p =
        reinterpret_cast<const float4*>(B + (size_t)blockIdx.x * (size_t)cols);
    const int n4 = cols >> 2;

    float s0 = 0.0f, s1 = 0.0f, s2 = 0.0f, s3 = 0.0f;
    int i = threadIdx.x;
    for (; i + 3 * BLOCK < n4; i += 4 * BLOCK) {
        float4 v0 = p[i];
        float4 v1 = p[i + BLOCK];
        float4 v2 = p[i + 2 * BLOCK];
        float4 v3 = p[i + 3 * BLOCK];
        s0 += (v0.x + v0.y) + (v0.z + v0.w);
        s1 += (v1.x + v1.y) + (v1.z + v1.w);
        s2 += (v2.x + v2.y) + (v2.z + v2.w);
        s3 += (v3.x + v3.y) + (v3.z + v3.w);
    }
    for (; i < n4; i += BLOCK) {
        float4 v = p[i];
        s0 += (v.x + v.y) + (v.z + v.w);
    }
    epilogue((s0 + s1) + (s2 + s3), out, ROWS);
}

extern "C" void kernel_launch(void* const* d_in, const int* in_sizes, int n_in,
                              void* d_out, int out_size)
{
    const float* B = (const float*)d_in[0];
    const int rows = ROWS;                   // 8192 per problem spec
    const int cols = in_sizes[0] / rows;     // 16384

    if (cols == COLS)
        bloss_unrolled_kernel<<<rows, BLOCK>>>(B, (float*)d_out);
    else
        bloss_generic_kernel<<<rows, BLOCK>>>(B, (float*)d_out, cols);
}

// round 11
// speedup vs baseline: 1.0570x; 1.0037x over previous
#include <cuda_runtime.h>

#define ROWS  8192
#define COLS  16384
#define BLOCK 512
#define NWARPS (BLOCK / 32)

// Allocation-free scratch: accumulator + completion counter.
__device__ float    g_acc   = 0.0f;
__device__ unsigned g_count = 0;

// LDG.128 non-coherent with L2 256B fetch-granularity hint.
__device__ __forceinline__ float4 ldg128_l2_256(const float4* __restrict__ a)
{
    float4 v;
    asm volatile("ld.global.nc.L2::256B.v4.f32 {%0, %1, %2, %3}, [%4];"
                 : "=f"(v.x), "=f"(v.y), "=f"(v.z), "=f"(v.w)
                 : "l"(a));
    return v;
}

__device__ __forceinline__ void epilogue(float s, float* __restrict__ out,
                                         int nblocks)
{
    // Warp reduce
    #pragma unroll
    for (int o = 16; o > 0; o >>= 1)
        s += __shfl_down_sync(0xffffffffu, s, o);

    __shared__ float ws[NWARPS];
    if ((threadIdx.x & 31) == 0) ws[threadIdx.x >> 5] = s;
    __syncthreads();

    if (threadIdx.x < 32) {
        // Warp-parallel tail: 16 partials reduced by shuffle tree.
        float t = (threadIdx.x < NWARPS) ? ws[threadIdx.x] : 0.0f;
        #pragma unroll
        for (int o = NWARPS / 2; o > 0; o >>= 1)
            t += __shfl_down_sync(0xffffffffu, t, o);

        if (threadIdx.x == 0) {
            float h = fmaxf(t - 1.0f, 0.0f);
            atomicAdd(&g_acc, h);
            // Release-ordered count increment: orders the g_acc add before
            // the counter bump without a full MEMBAR.GPU.
            unsigned done;
            asm volatile("atom.add.release.gpu.u32 %0, [%1], 1;"
                         : "=r"(done) : "l"(&g_count) : "memory");
            if (done == (unsigned)nblocks - 1u) {
                // Acquire-ordered read: all release-ordered g_acc adds visible.
                float total;
                asm volatile("ld.acquire.gpu.f32 %0, [%1];"
                             : "=f"(total) : "l"(&g_acc) : "memory");
                out[0] = total / (float)nblocks;
                // Reset for next graph replay.
                *(volatile float*)&g_acc = 0.0f;
                asm volatile("st.release.gpu.u32 [%0], 0;"
                             :: "l"(&g_count) : "memory");
            }
        }
    }
}

// One CTA per row, 512 threads, 8 fully-unrolled LDG.128 per thread, now
// with L2::256B fetch-granularity hint (halves LTS transaction count per
// byte on this perfectly-sequential stream).
__global__ void __launch_bounds__(BLOCK) bloss_unrolled_kernel(
    const float* __restrict__ B, float* __restrict__ out)
{
    const float4* __restrict__ p =
        reinterpret_cast<const float4*>(B + (size_t)blockIdx.x * COLS)
        + threadIdx.x;

    float4 v0 = ldg128_l2_256(p);
    float4 v1 = ldg128_l2_256(p + 1 * BLOCK);
    float4 v2 = ldg128_l2_256(p + 2 * BLOCK);
    float4 v3 = ldg128_l2_256(p + 3 * BLOCK);
    float4 v4 = ldg128_l2_256(p + 4 * BLOCK);
    float4 v5 = ldg128_l2_256(p + 5 * BLOCK);
    float4 v6 = ldg128_l2_256(p + 6 * BLOCK);
    float4 v7 = ldg128_l2_256(p + 7 * BLOCK);

    float s0 = (v0.x + v0.y) + (v0.z + v0.w);
    float s1 = (v1.x + v1.y) + (v1.z + v1.w);
    float s2 = (v2.x + v2.y) + (v2.z + v2.w);
    float s3 = (v3.x + v3.y) + (v3.z + v3.w);
    float s4 = (v4.x + v4.y) + (v4.z + v4.w);
    float s5 = (v5.x + v5.y) + (v5.z + v5.w);
    float s6 = (v6.x + v6.y) + (v6.z + v6.w);
    float s7 = (v7.x + v7.y) + (v7.z + v7.w);

    float s = ((s0 + s1) + (s2 + s3)) + ((s4 + s5) + (s6 + s7));
    epilogue(s, out, ROWS);
}

// Generic fallback (any cols divisible by 4): one row per CTA, LDG.128 loop.
__global__ void __launch_bounds__(BLOCK) bloss_generic_kernel(
    const float* __restrict__ B, float* __restrict__ out, int cols)
{
    const float4* __restrict__ p =
        reinterpret_cast<const float4*>(B + (size_t)blockIdx.x * (size_t)cols);
    const int n4 = cols >> 2;

    float s0 = 0.0f, s1 = 0.0f, s2 = 0.0f, s3 = 0.0f;
    int i = threadIdx.x;
    for (; i + 3 * BLOCK < n4; i += 4 * BLOCK) {
        float4 v0 = p[i];
        float4 v1 = p[i + BLOCK];
        float4 v2 = p[i + 2 * BLOCK];
        float4 v3 = p[i + 3 * BLOCK];
        s0 += (v0.x + v0.y) + (v0.z + v0.w);
        s1 += (v1.x + v1.y) + (v1.z + v1.w);
        s2 += (v2.x + v2.y) + (v2.z + v2.w);
        s3 += (v3.x + v3.y) + (v3.z + v3.w);
    }
    for (; i < n4; i += BLOCK) {
        float4 v = p[i];
        s0 += (v.x + v.y) + (v.z + v.w);
    }
    epilogue((s0 + s1) + (s2 + s3), out, ROWS);
}

extern "C" void kernel_launch(void* const* d_in, const int* in_sizes, int n_in,
                              void* d_out, int out_size)
{
    const float* B = (const float*)d_in[0];
    const int rows = ROWS;                   // 8192 per problem spec
    const int cols = in_sizes[0] / rows;     // 16384

    if (cols == COLS)
        bloss_unrolled_kernel<<<rows, BLOCK>>>(B, (float*)d_out);
    else
        bloss_generic_kernel<<<rows, BLOCK>>>(B, (float*)d_out, cols);
}